// round 16
// baseline (speedup 1.0000x reference)
#include <cuda_runtime.h>
#include <cuda_bf16.h>
#include <cstdint>
#include <math.h>

// Problem constants (fixed by setup_inputs)
#define T_LEN   4096
#define C_EMB   1024
#define NH      8
#define HD      128
#define WIN     1024

// Scratch (no cudaMalloc allowed)
__device__ float g_q[T_LEN * C_EMB];
__device__ float g_k[T_LEN * C_EMB];
__device__ float g_v[T_LEN * C_EMB];
__device__ float g_y[T_LEN * C_EMB];
__device__ float g_xr[T_LEN * C_EMB];            // tf32-rounded x
__device__ float g_wr[4][C_EMB * C_EMB];         // tf32-rounded wq,wk,wv,wp

__device__ __forceinline__ float f2tf32(float f) {
    unsigned int r;
    asm("cvt.rna.tf32.f32 %0, %1;" : "=r"(r) : "f"(f));
    return __uint_as_float(r);
}
__device__ __forceinline__ float fexp2(float x) {
    float y;
    asm("ex2.approx.f32 %0, %1;" : "=f"(y) : "f"(x));
    return y;
}

#define MMA_TF32(d, a, b)                                                     \
    asm volatile(                                                             \
        "mma.sync.aligned.m16n8k8.row.col.f32.tf32.tf32.f32 "                 \
        "{%0,%1,%2,%3},{%4,%5,%6,%7},{%8,%9},{%0,%1,%2,%3};\n"                \
        : "+f"(d[0]), "+f"(d[1]), "+f"(d[2]), "+f"(d[3])                      \
        : "r"(a[0]), "r"(a[1]), "r"(a[2]), "r"(a[3]), "r"(b[0]), "r"(b[1]))

__device__ __forceinline__ void cp_async16(void* smem_dst, const void* gmem_src) {
    unsigned int sa = (unsigned int)__cvta_generic_to_shared(smem_dst);
    asm volatile("cp.async.cg.shared.global [%0], [%1], 16;\n"
                 :: "r"(sa), "l"(gmem_src));
}
__device__ __forceinline__ void cp_async_commit() {
    asm volatile("cp.async.commit_group;\n");
}
template <int N>
__device__ __forceinline__ void cp_async_wait() {
    asm volatile("cp.async.wait_group %0;\n" :: "n"(N));
}

// ---------------------------------------------------------------------------
// tf32 pre-rounding kernels
// ---------------------------------------------------------------------------
__global__ __launch_bounds__(256) void round_x_kernel(
    const float* __restrict__ in, float* __restrict__ out)
{
    const int i = blockIdx.x * 256 + threadIdx.x;     // float4 index
    float4 v = ((const float4*)in)[i];
    v.x = f2tf32(v.x); v.y = f2tf32(v.y); v.z = f2tf32(v.z); v.w = f2tf32(v.w);
    ((float4*)out)[i] = v;
}

__global__ __launch_bounds__(256) void round_w_kernel(
    const float* __restrict__ w0, const float* __restrict__ w1,
    const float* __restrict__ w2, const float* __restrict__ w3,
    float* __restrict__ o)
{
    const float* in = (blockIdx.y == 0) ? w0 : (blockIdx.y == 1) ? w1 :
                      (blockIdx.y == 2) ? w2 : w3;
    float* out = o + (size_t)blockIdx.y * C_EMB * C_EMB;
    const int i = blockIdx.x * 256 + threadIdx.x;
    float4 v = ((const float4*)in)[i];
    v.x = f2tf32(v.x); v.y = f2tf32(v.y); v.z = f2tf32(v.z); v.w = f2tf32(v.w);
    ((float4*)out)[i] = v;
}

// ---------------------------------------------------------------------------
// tf32 tensor-core GEMM core: cp.async 2-stage, ONE __syncthreads per k-tile.
// BM=BN=128, BK=16, 128 thr = 4 warps (2x2), 64x64 per warp.
// Optional fused gate epilogue: C = tf32(acc + gate(x)·ve)  (V projection).
// ---------------------------------------------------------------------------
#define AS_STRIDE 20
#define BS_STRIDE 136
#define KTILES    (C_EMB / 16)

struct GemmSmem {
    float As[2][128 * AS_STRIDE];
    float Bs[2][16 * BS_STRIDE];
};

__device__ __forceinline__ void gemm_issue_tile(
    GemmSmem* sm, int stage, const float* __restrict__ Ag,
    const float* __restrict__ Bg, int k0, int tid)
{
    #pragma unroll
    for (int i = 0; i < 4; i++) {
        const int e  = tid + i * 128;        // 0..511
        const int ar = e >> 2, ac = (e & 3) << 2;
        cp_async16(&sm->As[stage][ar * AS_STRIDE + ac],
                   &Ag[(size_t)ar * C_EMB + k0 + ac]);
        const int br = e >> 5, bc = (e & 31) << 2;
        cp_async16(&sm->Bs[stage][br * BS_STRIDE + bc],
                   &Bg[(size_t)(k0 + br) * C_EMB + bc]);
    }
    cp_async_commit();
}

__device__ __forceinline__ void gemm_main(
    const float* __restrict__ Ag, const float* __restrict__ Bg,
    float* __restrict__ Cb,
    const float* __restrict__ xrow, const float* __restrict__ verow,
    const float* __restrict__ wgcol)
{
    __shared__ GemmSmem sm;

    const int tid  = threadIdx.x;
    const int lane = tid & 31;
    const int warp = tid >> 5;      // 0..3
    const int wm   = warp >> 1;
    const int wn   = warp & 1;
    const int gid  = lane >> 2;
    const int tig  = lane & 3;

    float acc[4][8][4];
    #pragma unroll
    for (int mi = 0; mi < 4; mi++)
        #pragma unroll
        for (int ni = 0; ni < 8; ni++)
            #pragma unroll
            for (int c = 0; c < 4; c++) acc[mi][ni][c] = 0.f;

    gemm_issue_tile(&sm, 0, Ag, Bg, 0, tid);

    for (int t = 0; t < KTILES; t++) {
        const int cur = t & 1;
        cp_async_wait<0>();          // tile t resident (only pending group)
        __syncthreads();             // all warps done with buffer cur^1
        if (t + 1 < KTILES)
            gemm_issue_tile(&sm, cur ^ 1, Ag, Bg, (t + 1) * 16, tid);

        const float* As = sm.As[cur];
        const float* Bs = sm.Bs[cur];
        #pragma unroll
        for (int ks = 0; ks < 2; ks++) {
            const int kb = ks * 8;
            unsigned int af[4][4], bf[8][2];
            #pragma unroll
            for (int mi = 0; mi < 4; mi++) {
                const int r = wm * 64 + mi * 16 + gid;
                af[mi][0] = __float_as_uint(As[(r    ) * AS_STRIDE + kb + tig    ]);
                af[mi][1] = __float_as_uint(As[(r + 8) * AS_STRIDE + kb + tig    ]);
                af[mi][2] = __float_as_uint(As[(r    ) * AS_STRIDE + kb + tig + 4]);
                af[mi][3] = __float_as_uint(As[(r + 8) * AS_STRIDE + kb + tig + 4]);
            }
            #pragma unroll
            for (int ni = 0; ni < 8; ni++) {
                const int c = wn * 64 + ni * 8 + gid;
                bf[ni][0] = __float_as_uint(Bs[(kb + tig    ) * BS_STRIDE + c]);
                bf[ni][1] = __float_as_uint(Bs[(kb + tig + 4) * BS_STRIDE + c]);
            }
            #pragma unroll
            for (int mi = 0; mi < 4; mi++)
                #pragma unroll
                for (int ni = 0; ni < 8; ni++)
                    MMA_TF32(acc[mi][ni], af[mi], bf[ni]);
        }
    }

    // optional fused gate: gate[r] = 2*sigmoid(x[r,0:32]·wg[:,h]); C = tf32(acc+gate*ve)
    float gate0[4], gate1[4];
    if (xrow) {
        __syncthreads();                    // frag reads of As done everywhere
        float* xs = (float*)sm.As;          // reuse: 128*33 + 32 floats
        #pragma unroll
        for (int i = 0; i < 8; i++) {
            const int e4 = i * 128 + tid;
            const int r  = e4 >> 3;
            const int c4 = (e4 & 7) << 2;
            float4 xv = *(const float4*)&xrow[(size_t)r * C_EMB + c4];
            xs[r * 33 + c4 + 0] = xv.x;
            xs[r * 33 + c4 + 1] = xv.y;
            xs[r * 33 + c4 + 2] = xv.z;
            xs[r * 33 + c4 + 3] = xv.w;
        }
        if (tid < 32) xs[128 * 33 + tid] = wgcol[tid * NH];
        __syncthreads();
        #pragma unroll
        for (int mi = 0; mi < 4; mi++) {
            const int r = wm * 64 + mi * 16 + gid;
            float ga = 0.f, gb = 0.f;
            #pragma unroll
            for (int c = 0; c < 32; c++) {
                const float w = xs[128 * 33 + c];
                ga = fmaf(xs[(r    ) * 33 + c], w, ga);
                gb = fmaf(xs[(r + 8) * 33 + c], w, gb);
            }
            gate0[mi] = 2.f / (1.f + expf(-ga));
            gate1[mi] = 2.f / (1.f + expf(-gb));
        }
    }

    #pragma unroll
    for (int mi = 0; mi < 4; mi++) {
        const int row = wm * 64 + mi * 16 + gid;
        #pragma unroll
        for (int ni = 0; ni < 8; ni++) {
            const int col = wn * 64 + ni * 8 + 2 * tig;
            float2 o0 = make_float2(acc[mi][ni][0], acc[mi][ni][1]);
            float2 o1 = make_float2(acc[mi][ni][2], acc[mi][ni][3]);
            if (xrow) {
                float2 va = *(const float2*)&verow[(size_t)(row    ) * C_EMB + col];
                float2 vb = *(const float2*)&verow[(size_t)(row + 8) * C_EMB + col];
                o0.x = f2tf32(fmaf(gate0[mi], va.x, o0.x));
                o0.y = f2tf32(fmaf(gate0[mi], va.y, o0.y));
                o1.x = f2tf32(fmaf(gate1[mi], vb.x, o1.x));
                o1.y = f2tf32(fmaf(gate1[mi], vb.y, o1.y));
            }
            *(float2*)&Cb[(size_t)(row    ) * C_EMB + col] = o0;
            *(float2*)&Cb[(size_t)(row + 8) * C_EMB + col] = o1;
        }
    }
}

// Fused QKV projection (+gate on V): grid.x = 24, grid.y = 32. BM=128.
__global__ __launch_bounds__(128) void qkv_gemm_kernel(
    const float* __restrict__ A,        // rounded x
    const float* __restrict__ Wr,       // rounded weights base (g_wr)
    float* __restrict__ C0, float* __restrict__ C1, float* __restrict__ C2,
    const float* __restrict__ xraw, const float* __restrict__ ve,
    const float* __restrict__ wg)
{
    const int sel = blockIdx.x >> 3;
    const int bxn = blockIdx.x & 7;
    const float* B = Wr + (size_t)sel * C_EMB * C_EMB;
    float*       C = (sel == 0) ? C0 : (sel == 1) ? C1 : C2;

    const size_t rowoff = (size_t)blockIdx.y * 128 * C_EMB;
    const float* Ag = A + rowoff;
    const float* Bg = B + bxn * 128;
    float*       Cb = C + rowoff + bxn * 128;

    if (sel == 2) {
        gemm_main(Ag, Bg, Cb, xraw + rowoff, ve + rowoff + bxn * 128, wg + bxn);
    } else {
        gemm_main(Ag, Bg, Cb, nullptr, nullptr, nullptr);
    }
}

// Output projection: BM=128, grid (8, 32).
__global__ __launch_bounds__(128) void tf32_gemm_kernel(
    const float* __restrict__ A, const float* __restrict__ B,
    float* __restrict__ C)
{
    const float* Ag = A + (size_t)blockIdx.y * 128 * C_EMB;
    const float* Bg = B + blockIdx.x * 128;
    float*       Cb = C + (size_t)blockIdx.y * 128 * C_EMB + blockIdx.x * 128;
    gemm_main(Ag, Bg, Cb, nullptr, nullptr, nullptr);
}

// ---------------------------------------------------------------------------
// RoPE + RMSNorm, q and k in one launch. Outputs tf32-rounded.
// q additionally scaled by log2(e)/sqrt(HD) (softmax runs in exp2 domain).
// ---------------------------------------------------------------------------
__global__ __launch_bounds__(256) void rope_rms2_kernel(
    float* __restrict__ qp, float* __restrict__ kp,
    const float* __restrict__ cosb, const float* __restrict__ sinb)
{
    const int t = blockIdx.x;
    float* p = blockIdx.y ? kp : qp;
    const float oscale = blockIdx.y ? 1.0f
                       : 0.08838834764831845f * 1.4426950408889634f;
    const int warp = threadIdx.x >> 5;   // head 0..7
    const int lane = threadIdx.x & 31;
    const size_t base = (size_t)t * C_EMB + warp * HD;
    const int dd = lane * 2;

    const float2 cs = *(const float2*)&cosb[t * 64 + dd];
    const float2 sn = *(const float2*)&sinb[t * 64 + dd];
    const float2 xa = *(const float2*)&p[base + dd];
    const float2 xb = *(const float2*)&p[base + dd + 64];
    float2 y1 = make_float2( xa.x * cs.x + xb.x * sn.x,  xa.y * cs.y + xb.y * sn.y);
    float2 y2 = make_float2(-xa.x * sn.x + xb.x * cs.x, -xa.y * sn.y + xb.y * cs.y);

    float ss = y1.x * y1.x + y1.y * y1.y + y2.x * y2.x + y2.y * y2.y;
    #pragma unroll
    for (int o = 16; o; o >>= 1) ss += __shfl_xor_sync(0xffffffffu, ss, o);
    const float r = rsqrtf(ss * (1.f / HD) + 1e-6f) * oscale;

    *(float2*)&p[base + dd]      = make_float2(f2tf32(y1.x * r), f2tf32(y1.y * r));
    *(float2*)&p[base + dd + 64] = make_float2(f2tf32(y2.x * r), f2tf32(y2.y * r));
}

// ---------------------------------------------------------------------------
// Tensor-core sliding-window flash attention (unchanged from round 12 pass).
// ---------------------------------------------------------------------------
#define AQT 128
#define AKT 32
#define KSTR 132
#define VSTR 136
#define PSTR 36

__global__ __launch_bounds__(256) void attn_mma_kernel(
    const float* __restrict__ q, const float* __restrict__ k,
    const float* __restrict__ v, float* __restrict__ y)
{
    __shared__ float KsPs[8 * 16 * PSTR];
    __shared__ float Vs[AKT * VSTR];

    const int h    = blockIdx.y;
    const int t0   = blockIdx.x * AQT;
    const int tid  = threadIdx.x;
    const int warp = tid >> 5;
    const int lane = tid & 31;
    const int gid  = lane >> 2;
    const int tig  = lane & 3;

    const int gq0 = t0 + warp * 16 + gid;
    const int gq1 = gq0 + 8;

    unsigned int qfrag[16][4];
    {
        const float* q0p = q + (size_t)gq0 * C_EMB + h * HD;
        const float* q1p = q + (size_t)gq1 * C_EMB + h * HD;
        #pragma unroll
        for (int kk = 0; kk < 16; kk++) {
            const int kb = kk * 8;
            qfrag[kk][0] = __float_as_uint(q0p[kb + tig    ]);
            qfrag[kk][1] = __float_as_uint(q1p[kb + tig    ]);
            qfrag[kk][2] = __float_as_uint(q0p[kb + tig + 4]);
            qfrag[kk][3] = __float_as_uint(q1p[kb + tig + 4]);
        }
    }

    float oacc[16][4];
    #pragma unroll
    for (int nt = 0; nt < 16; nt++)
        #pragma unroll
        for (int c = 0; c < 4; c++) oacc[nt][c] = 0.f;
    float m0 = -1e30f, m1 = -1e30f, l0 = 0.f, l1 = 0.f;

    int ks0 = t0 - (WIN - 1);
    if (ks0 < 0) ks0 = 0;
    ks0 &= ~(AKT - 1);

    float* Pw = KsPs + warp * 16 * PSTR;

    for (int ks = ks0; ks <= t0 + AQT - 1; ks += AKT) {
        __syncthreads();
        #pragma unroll
        for (int i = 0; i < 4; i++) {
            const int e4  = i * 256 + tid;
            const int row = e4 >> 5;
            const int c4  = (e4 & 31) << 2;
            float4 kv = *(const float4*)&k[(size_t)(ks + row) * C_EMB + h * HD + c4];
            *(float4*)&KsPs[row * KSTR + c4] = kv;
            float4 vv = *(const float4*)&v[(size_t)(ks + row) * C_EMB + h * HD + c4];
            *(float4*)&Vs[row * VSTR + c4] = vv;
        }
        __syncthreads();

        float sacc[4][4];
        #pragma unroll
        for (int nt = 0; nt < 4; nt++)
            #pragma unroll
            for (int c = 0; c < 4; c++) sacc[nt][c] = 0.f;

        #pragma unroll
        for (int kk = 0; kk < 16; kk++) {
            const int kb = kk * 8;
            #pragma unroll
            for (int nt = 0; nt < 4; nt++) {
                const int key = nt * 8 + gid;
                unsigned int bf[2];
                bf[0] = __float_as_uint(KsPs[key * KSTR + kb + tig    ]);
                bf[1] = __float_as_uint(KsPs[key * KSTR + kb + tig + 4]);
                MMA_TF32(sacc[nt], qfrag[kk], bf);
            }
        }

        float p[4][4];
        float tmax0 = -1e30f, tmax1 = -1e30f;
        bool  vmask[4][4];
        #pragma unroll
        for (int nt = 0; nt < 4; nt++) {
            #pragma unroll
            for (int c = 0; c < 4; c++) {
                const int key = ks + nt * 8 + 2 * tig + (c & 1);
                const int gq  = (c < 2) ? gq0 : gq1;
                const bool valid = (key <= gq) && (key > gq - WIN);
                vmask[nt][c] = valid;
                const float s = valid ? sacc[nt][c] : -1e30f;
                sacc[nt][c] = s;
                if (c < 2) tmax0 = fmaxf(tmax0, s);
                else       tmax1 = fmaxf(tmax1, s);
            }
        }
        #pragma unroll
        for (int o = 1; o <= 2; o <<= 1) {
            tmax0 = fmaxf(tmax0, __shfl_xor_sync(0xffffffffu, tmax0, o));
            tmax1 = fmaxf(tmax1, __shfl_xor_sync(0xffffffffu, tmax1, o));
        }
        const float mn0 = fmaxf(m0, tmax0);
        const float mn1 = fmaxf(m1, tmax1);
        const float alpha0 = fexp2(m0 - mn0);
        const float alpha1 = fexp2(m1 - mn1);
        m0 = mn0; m1 = mn1;

        float rs0 = 0.f, rs1 = 0.f;
        #pragma unroll
        for (int nt = 0; nt < 4; nt++) {
            #pragma unroll
            for (int c = 0; c < 4; c++) {
                const float mn = (c < 2) ? mn0 : mn1;
                const float pv = vmask[nt][c] ? fexp2(sacc[nt][c] - mn) : 0.f;
                p[nt][c] = pv;
                if (c < 2) rs0 += pv; else rs1 += pv;
            }
        }
        #pragma unroll
        for (int o = 1; o <= 2; o <<= 1) {
            rs0 += __shfl_xor_sync(0xffffffffu, rs0, o);
            rs1 += __shfl_xor_sync(0xffffffffu, rs1, o);
        }
        l0 = l0 * alpha0 + rs0;
        l1 = l1 * alpha1 + rs1;

        #pragma unroll
        for (int nt = 0; nt < 16; nt++) {
            oacc[nt][0] *= alpha0; oacc[nt][1] *= alpha0;
            oacc[nt][2] *= alpha1; oacc[nt][3] *= alpha1;
        }

        __syncthreads();

        #pragma unroll
        for (int nt = 0; nt < 4; nt++) {
            const int col = nt * 8 + 2 * tig;
            *(float2*)&Pw[(gid    ) * PSTR + col] = make_float2(f2tf32(p[nt][0]), f2tf32(p[nt][1]));
            *(float2*)&Pw[(gid + 8) * PSTR + col] = make_float2(f2tf32(p[nt][2]), f2tf32(p[nt][3]));
        }
        __syncwarp();

        #pragma unroll
        for (int kk = 0; kk < 4; kk++) {
            const int kb = kk * 8;
            unsigned int pa[4];
            pa[0] = __float_as_uint(Pw[(gid    ) * PSTR + kb + tig    ]);
            pa[1] = __float_as_uint(Pw[(gid + 8) * PSTR + kb + tig    ]);
            pa[2] = __float_as_uint(Pw[(gid    ) * PSTR + kb + tig + 4]);
            pa[3] = __float_as_uint(Pw[(gid + 8) * PSTR + kb + tig + 4]);
            #pragma unroll
            for (int nt = 0; nt < 16; nt++) {
                unsigned int vb[2];
                vb[0] = __float_as_uint(Vs[(kb + tig    ) * VSTR + nt * 8 + gid]);
                vb[1] = __float_as_uint(Vs[(kb + tig + 4) * VSTR + nt * 8 + gid]);
                MMA_TF32(oacc[nt], pa, vb);
            }
        }
    }

    const float il0 = 1.f / l0;
    const float il1 = 1.f / l1;
    #pragma unroll
    for (int nt = 0; nt < 16; nt++) {
        const int col = nt * 8 + 2 * tig;
        *(float2*)&y[(size_t)gq0 * C_EMB + h * HD + col] =
            make_float2(f2tf32(oacc[nt][0] * il0), f2tf32(oacc[nt][1] * il0));
        *(float2*)&y[(size_t)gq1 * C_EMB + h * HD + col] =
            make_float2(f2tf32(oacc[nt][2] * il1), f2tf32(oacc[nt][3] * il1));
    }
}

// ---------------------------------------------------------------------------
extern "C" void kernel_launch(void* const* d_in, const int* in_sizes, int n_in,
                              void* d_out, int out_size)
{
    const float* x    = (const float*)d_in[0];
    const float* ve   = (const float*)d_in[1];
    const float* cosb = (const float*)d_in[2];
    const float* sinb = (const float*)d_in[3];
    const float* wq   = (const float*)d_in[4];
    const float* wk   = (const float*)d_in[5];
    const float* wv   = (const float*)d_in[6];
    const float* wg   = (const float*)d_in[7];
    const float* wp   = (const float*)d_in[8];
    float* out = (float*)d_out;

    float *q, *k, *v, *y, *xr, *wr;
    cudaGetSymbolAddress((void**)&q,  g_q);
    cudaGetSymbolAddress((void**)&k,  g_k);
    cudaGetSymbolAddress((void**)&v,  g_v);
    cudaGetSymbolAddress((void**)&y,  g_y);
    cudaGetSymbolAddress((void**)&xr, g_xr);
    cudaGetSymbolAddress((void**)&wr, g_wr);

    // 0. pre-round x and weights to tf32
    round_x_kernel<<<T_LEN * C_EMB / 4 / 256, 256>>>(x, xr);
    dim3 rw_grid(C_EMB * C_EMB / 4 / 256, 4);
    round_w_kernel<<<rw_grid, 256>>>(wq, wk, wv, wp, wr);

    // 1. fused QKV projections (+gate on V)
    dim3 qkv_grid(24, T_LEN / 128);
    qkv_gemm_kernel<<<qkv_grid, 128>>>(xr, wr, q, k, v, x, ve, wg);

    // 2. RoPE + RMSNorm on q and k
    dim3 rr_grid(T_LEN, 2);
    rope_rms2_kernel<<<rr_grid, 256>>>(q, k, cosb, sinb);

    // 3. tensor-core sliding-window attention
    dim3 attn_grid(T_LEN / AQT, NH);        // (32, 8)
    attn_mma_kernel<<<attn_grid, 256>>>(q, k, v, y);

    // 4. output projection (BM=128, grid (8,32))
    dim3 gemm_grid(C_EMB / 128, T_LEN / 128);
    tf32_gemm_kernel<<<gemm_grid, 128>>>(y, wr + (size_t)3 * C_EMB * C_EMB, out);
}

// round 17
// speedup vs baseline: 1.5442x; 1.5442x over previous
#include <cuda_runtime.h>
#include <cuda_bf16.h>
#include <cstdint>
#include <math.h>

// Problem constants (fixed by setup_inputs)
#define T_LEN   4096
#define C_EMB   1024
#define NH      8
#define HD      128
#define WIN     1024

// Scratch (no cudaMalloc allowed)
__device__ float g_q[T_LEN * C_EMB];
__device__ float g_k[T_LEN * C_EMB];
__device__ float g_v[T_LEN * C_EMB];
__device__ float g_y[T_LEN * C_EMB];
__device__ float g_xr[T_LEN * C_EMB];            // tf32-rounded x
__device__ float g_wr[4][C_EMB * C_EMB];         // tf32-rounded wq,wk,wv,wp

__device__ __forceinline__ float f2tf32(float f) {
    unsigned int r;
    asm("cvt.rna.tf32.f32 %0, %1;" : "=r"(r) : "f"(f));
    return __uint_as_float(r);
}
__device__ __forceinline__ float fexp2(float x) {
    float y;
    asm("ex2.approx.f32 %0, %1;" : "=f"(y) : "f"(x));
    return y;
}

#define MMA_TF32(d, a, b)                                                     \
    asm volatile(                                                             \
        "mma.sync.aligned.m16n8k8.row.col.f32.tf32.tf32.f32 "                 \
        "{%0,%1,%2,%3},{%4,%5,%6,%7},{%8,%9},{%0,%1,%2,%3};\n"                \
        : "+f"(d[0]), "+f"(d[1]), "+f"(d[2]), "+f"(d[3])                      \
        : "r"(a[0]), "r"(a[1]), "r"(a[2]), "r"(a[3]), "r"(b[0]), "r"(b[1]))

__device__ __forceinline__ void cp_async16(void* smem_dst, const void* gmem_src) {
    unsigned int sa = (unsigned int)__cvta_generic_to_shared(smem_dst);
    asm volatile("cp.async.cg.shared.global [%0], [%1], 16;\n"
                 :: "r"(sa), "l"(gmem_src));
}
__device__ __forceinline__ void cp_async_commit() {
    asm volatile("cp.async.commit_group;\n");
}
template <int N>
__device__ __forceinline__ void cp_async_wait() {
    asm volatile("cp.async.wait_group %0;\n" :: "n"(N));
}

// ---------------------------------------------------------------------------
// tf32 pre-rounding: ONE kernel for x and all 4 weights.
// grid (1024, 8): y<4 -> quarter of x; y>=4 -> weight y-4. 256 thr, float4.
// ---------------------------------------------------------------------------
__global__ __launch_bounds__(256) void round_all_kernel(
    const float* __restrict__ x,
    const float* __restrict__ w0, const float* __restrict__ w1,
    const float* __restrict__ w2, const float* __restrict__ w3,
    float* __restrict__ xr, float* __restrict__ wr)
{
    const int i = blockIdx.x * 256 + threadIdx.x;     // 0..262143 float4s
    const int yb = blockIdx.y;
    const float4* src;
    float4* dst;
    if (yb < 4) {
        src = (const float4*)x  + (size_t)yb * 262144 + i;
        dst = (float4*)xr       + (size_t)yb * 262144 + i;
    } else {
        const int s = yb - 4;
        const float* w = (s == 0) ? w0 : (s == 1) ? w1 : (s == 2) ? w2 : w3;
        src = (const float4*)w  + i;
        dst = (float4*)wr       + (size_t)s * 262144 + i;
    }
    float4 v = *src;
    v.x = f2tf32(v.x); v.y = f2tf32(v.y); v.z = f2tf32(v.z); v.w = f2tf32(v.w);
    *dst = v;
}

// ---------------------------------------------------------------------------
// tf32 tensor-core GEMM core — EXACT R12 loop structure (proven 471.9us):
// issue(t+1) -> wait<1> -> sync -> compute -> sync. cp.async 2-stage.
// BM=BN=128, BK=16, 128 thr = 4 warps (2x2), 64x64 per warp.
// Optional fused gate epilogue: C = tf32(acc + gate(x)·ve)  (V projection).
// ---------------------------------------------------------------------------
#define AS_STRIDE 20
#define BS_STRIDE 136
#define KTILES    (C_EMB / 16)

struct GemmSmem {
    float As[2][128 * AS_STRIDE];
    float Bs[2][16 * BS_STRIDE];
};

__device__ __forceinline__ void gemm_issue_tile(
    GemmSmem* sm, int stage, const float* __restrict__ Ag,
    const float* __restrict__ Bg, int k0, int tid)
{
    #pragma unroll
    for (int i = 0; i < 4; i++) {
        const int e  = tid + i * 128;        // 0..511
        const int ar = e >> 2, ac = (e & 3) << 2;
        cp_async16(&sm->As[stage][ar * AS_STRIDE + ac],
                   &Ag[(size_t)ar * C_EMB + k0 + ac]);
        const int br = e >> 5, bc = (e & 31) << 2;
        cp_async16(&sm->Bs[stage][br * BS_STRIDE + bc],
                   &Bg[(size_t)(k0 + br) * C_EMB + bc]);
    }
    cp_async_commit();
}

__device__ __forceinline__ void gemm_main(
    const float* __restrict__ Ag, const float* __restrict__ Bg,
    float* __restrict__ Cb,
    const float* __restrict__ xrow, const float* __restrict__ verow,
    const float* __restrict__ wgcol)
{
    __shared__ GemmSmem sm;

    const int tid  = threadIdx.x;
    const int lane = tid & 31;
    const int warp = tid >> 5;      // 0..3
    const int wm   = warp >> 1;
    const int wn   = warp & 1;
    const int gid  = lane >> 2;
    const int tig  = lane & 3;

    float acc[4][8][4];
    #pragma unroll
    for (int mi = 0; mi < 4; mi++)
        #pragma unroll
        for (int ni = 0; ni < 8; ni++)
            #pragma unroll
            for (int c = 0; c < 4; c++) acc[mi][ni][c] = 0.f;

    gemm_issue_tile(&sm, 0, Ag, Bg, 0, tid);

    for (int t = 0; t < KTILES; t++) {
        const int cur = t & 1;
        if (t + 1 < KTILES)
            gemm_issue_tile(&sm, cur ^ 1, Ag, Bg, (t + 1) * 16, tid);
        if (t + 1 < KTILES) cp_async_wait<1>(); else cp_async_wait<0>();
        __syncthreads();

        const float* As = sm.As[cur];
        const float* Bs = sm.Bs[cur];
        #pragma unroll
        for (int ks = 0; ks < 2; ks++) {
            const int kb = ks * 8;
            unsigned int af[4][4], bf[8][2];
            #pragma unroll
            for (int mi = 0; mi < 4; mi++) {
                const int r = wm * 64 + mi * 16 + gid;
                af[mi][0] = __float_as_uint(As[(r    ) * AS_STRIDE + kb + tig    ]);
                af[mi][1] = __float_as_uint(As[(r + 8) * AS_STRIDE + kb + tig    ]);
                af[mi][2] = __float_as_uint(As[(r    ) * AS_STRIDE + kb + tig + 4]);
                af[mi][3] = __float_as_uint(As[(r + 8) * AS_STRIDE + kb + tig + 4]);
            }
            #pragma unroll
            for (int ni = 0; ni < 8; ni++) {
                const int c = wn * 64 + ni * 8 + gid;
                bf[ni][0] = __float_as_uint(Bs[(kb + tig    ) * BS_STRIDE + c]);
                bf[ni][1] = __float_as_uint(Bs[(kb + tig + 4) * BS_STRIDE + c]);
            }
            #pragma unroll
            for (int mi = 0; mi < 4; mi++)
                #pragma unroll
                for (int ni = 0; ni < 8; ni++)
                    MMA_TF32(acc[mi][ni], af[mi], bf[ni]);
        }
        __syncthreads();
    }

    // optional fused gate: gate[r] = 2*sigmoid(x[r,0:32]·wg[:,h]); C = tf32(acc+gate*ve)
    float gate0[4], gate1[4];
    if (xrow) {
        float* xs = (float*)sm.As;          // reuse: 128*33 + 32 floats
        #pragma unroll
        for (int i = 0; i < 8; i++) {
            const int e4 = i * 128 + tid;
            const int r  = e4 >> 3;
            const int c4 = (e4 & 7) << 2;
            float4 xv = *(const float4*)&xrow[(size_t)r * C_EMB + c4];
            xs[r * 33 + c4 + 0] = xv.x;
            xs[r * 33 + c4 + 1] = xv.y;
            xs[r * 33 + c4 + 2] = xv.z;
            xs[r * 33 + c4 + 3] = xv.w;
        }
        if (tid < 32) xs[128 * 33 + tid] = wgcol[tid * NH];
        __syncthreads();
        #pragma unroll
        for (int mi = 0; mi < 4; mi++) {
            const int r = wm * 64 + mi * 16 + gid;
            float ga = 0.f, gb = 0.f;
            #pragma unroll
            for (int c = 0; c < 32; c++) {
                const float w = xs[128 * 33 + c];
                ga = fmaf(xs[(r    ) * 33 + c], w, ga);
                gb = fmaf(xs[(r + 8) * 33 + c], w, gb);
            }
            gate0[mi] = 2.f / (1.f + expf(-ga));
            gate1[mi] = 2.f / (1.f + expf(-gb));
        }
    }

    #pragma unroll
    for (int mi = 0; mi < 4; mi++) {
        const int row = wm * 64 + mi * 16 + gid;
        #pragma unroll
        for (int ni = 0; ni < 8; ni++) {
            const int col = wn * 64 + ni * 8 + 2 * tig;
            float2 o0 = make_float2(acc[mi][ni][0], acc[mi][ni][1]);
            float2 o1 = make_float2(acc[mi][ni][2], acc[mi][ni][3]);
            if (xrow) {
                float2 va = *(const float2*)&verow[(size_t)(row    ) * C_EMB + col];
                float2 vb = *(const float2*)&verow[(size_t)(row + 8) * C_EMB + col];
                o0.x = f2tf32(fmaf(gate0[mi], va.x, o0.x));
                o0.y = f2tf32(fmaf(gate0[mi], va.y, o0.y));
                o1.x = f2tf32(fmaf(gate1[mi], vb.x, o1.x));
                o1.y = f2tf32(fmaf(gate1[mi], vb.y, o1.y));
            }
            *(float2*)&Cb[(size_t)(row    ) * C_EMB + col] = o0;
            *(float2*)&Cb[(size_t)(row + 8) * C_EMB + col] = o1;
        }
    }
}

// Fused QKV projection (+gate on V): grid.x = 24, grid.y = 32. BM=128.
__global__ __launch_bounds__(128) void qkv_gemm_kernel(
    const float* __restrict__ A,        // rounded x
    const float* __restrict__ Wr,       // rounded weights base (g_wr)
    float* __restrict__ C0, float* __restrict__ C1, float* __restrict__ C2,
    const float* __restrict__ xraw, const float* __restrict__ ve,
    const float* __restrict__ wg)
{
    const int sel = blockIdx.x >> 3;
    const int bxn = blockIdx.x & 7;
    const float* B = Wr + (size_t)sel * C_EMB * C_EMB;
    float*       C = (sel == 0) ? C0 : (sel == 1) ? C1 : C2;

    const size_t rowoff = (size_t)blockIdx.y * 128 * C_EMB;
    const float* Ag = A + rowoff;
    const float* Bg = B + bxn * 128;
    float*       Cb = C + rowoff + bxn * 128;

    if (sel == 2) {
        gemm_main(Ag, Bg, Cb, xraw + rowoff, ve + rowoff + bxn * 128, wg + bxn);
    } else {
        gemm_main(Ag, Bg, Cb, nullptr, nullptr, nullptr);
    }
}

// Output projection: BM=128, grid (8, 32).
__global__ __launch_bounds__(128) void tf32_gemm_kernel(
    const float* __restrict__ A, const float* __restrict__ B,
    float* __restrict__ C)
{
    const float* Ag = A + (size_t)blockIdx.y * 128 * C_EMB;
    const float* Bg = B + blockIdx.x * 128;
    float*       Cb = C + (size_t)blockIdx.y * 128 * C_EMB + blockIdx.x * 128;
    gemm_main(Ag, Bg, Cb, nullptr, nullptr, nullptr);
}

// ---------------------------------------------------------------------------
// RoPE + RMSNorm, q and k in one launch. Outputs tf32-rounded.
// q additionally scaled by log2(e)/sqrt(HD) (softmax runs in exp2 domain).
// ---------------------------------------------------------------------------
__global__ __launch_bounds__(256) void rope_rms2_kernel(
    float* __restrict__ qp, float* __restrict__ kp,
    const float* __restrict__ cosb, const float* __restrict__ sinb)
{
    const int t = blockIdx.x;
    float* p = blockIdx.y ? kp : qp;
    const float oscale = blockIdx.y ? 1.0f
                       : 0.08838834764831845f * 1.4426950408889634f;
    const int warp = threadIdx.x >> 5;   // head 0..7
    const int lane = threadIdx.x & 31;
    const size_t base = (size_t)t * C_EMB + warp * HD;
    const int dd = lane * 2;

    const float2 cs = *(const float2*)&cosb[t * 64 + dd];
    const float2 sn = *(const float2*)&sinb[t * 64 + dd];
    const float2 xa = *(const float2*)&p[base + dd];
    const float2 xb = *(const float2*)&p[base + dd + 64];
    float2 y1 = make_float2( xa.x * cs.x + xb.x * sn.x,  xa.y * cs.y + xb.y * sn.y);
    float2 y2 = make_float2(-xa.x * sn.x + xb.x * cs.x, -xa.y * sn.y + xb.y * cs.y);

    float ss = y1.x * y1.x + y1.y * y1.y + y2.x * y2.x + y2.y * y2.y;
    #pragma unroll
    for (int o = 16; o; o >>= 1) ss += __shfl_xor_sync(0xffffffffu, ss, o);
    const float r = rsqrtf(ss * (1.f / HD) + 1e-6f) * oscale;

    *(float2*)&p[base + dd]      = make_float2(f2tf32(y1.x * r), f2tf32(y1.y * r));
    *(float2*)&p[base + dd + 64] = make_float2(f2tf32(y2.x * r), f2tf32(y2.y * r));
}

// ---------------------------------------------------------------------------
// Tensor-core sliding-window flash attention (unchanged from round 12 pass).
// ---------------------------------------------------------------------------
#define AQT 128
#define AKT 32
#define KSTR 132
#define VSTR 136
#define PSTR 36

__global__ __launch_bounds__(256) void attn_mma_kernel(
    const float* __restrict__ q, const float* __restrict__ k,
    const float* __restrict__ v, float* __restrict__ y)
{
    __shared__ float KsPs[8 * 16 * PSTR];
    __shared__ float Vs[AKT * VSTR];

    const int h    = blockIdx.y;
    const int t0   = blockIdx.x * AQT;
    const int tid  = threadIdx.x;
    const int warp = tid >> 5;
    const int lane = tid & 31;
    const int gid  = lane >> 2;
    const int tig  = lane & 3;

    const int gq0 = t0 + warp * 16 + gid;
    const int gq1 = gq0 + 8;

    unsigned int qfrag[16][4];
    {
        const float* q0p = q + (size_t)gq0 * C_EMB + h * HD;
        const float* q1p = q + (size_t)gq1 * C_EMB + h * HD;
        #pragma unroll
        for (int kk = 0; kk < 16; kk++) {
            const int kb = kk * 8;
            qfrag[kk][0] = __float_as_uint(q0p[kb + tig    ]);
            qfrag[kk][1] = __float_as_uint(q1p[kb + tig    ]);
            qfrag[kk][2] = __float_as_uint(q0p[kb + tig + 4]);
            qfrag[kk][3] = __float_as_uint(q1p[kb + tig + 4]);
        }
    }

    float oacc[16][4];
    #pragma unroll
    for (int nt = 0; nt < 16; nt++)
        #pragma unroll
        for (int c = 0; c < 4; c++) oacc[nt][c] = 0.f;
    float m0 = -1e30f, m1 = -1e30f, l0 = 0.f, l1 = 0.f;

    int ks0 = t0 - (WIN - 1);
    if (ks0 < 0) ks0 = 0;
    ks0 &= ~(AKT - 1);

    float* Pw = KsPs + warp * 16 * PSTR;

    for (int ks = ks0; ks <= t0 + AQT - 1; ks += AKT) {
        __syncthreads();
        #pragma unroll
        for (int i = 0; i < 4; i++) {
            const int e4  = i * 256 + tid;
            const int row = e4 >> 5;
            const int c4  = (e4 & 31) << 2;
            float4 kv = *(const float4*)&k[(size_t)(ks + row) * C_EMB + h * HD + c4];
            *(float4*)&KsPs[row * KSTR + c4] = kv;
            float4 vv = *(const float4*)&v[(size_t)(ks + row) * C_EMB + h * HD + c4];
            *(float4*)&Vs[row * VSTR + c4] = vv;
        }
        __syncthreads();

        float sacc[4][4];
        #pragma unroll
        for (int nt = 0; nt < 4; nt++)
            #pragma unroll
            for (int c = 0; c < 4; c++) sacc[nt][c] = 0.f;

        #pragma unroll
        for (int kk = 0; kk < 16; kk++) {
            const int kb = kk * 8;
            #pragma unroll
            for (int nt = 0; nt < 4; nt++) {
                const int key = nt * 8 + gid;
                unsigned int bf[2];
                bf[0] = __float_as_uint(KsPs[key * KSTR + kb + tig    ]);
                bf[1] = __float_as_uint(KsPs[key * KSTR + kb + tig + 4]);
                MMA_TF32(sacc[nt], qfrag[kk], bf);
            }
        }

        float p[4][4];
        float tmax0 = -1e30f, tmax1 = -1e30f;
        bool  vmask[4][4];
        #pragma unroll
        for (int nt = 0; nt < 4; nt++) {
            #pragma unroll
            for (int c = 0; c < 4; c++) {
                const int key = ks + nt * 8 + 2 * tig + (c & 1);
                const int gq  = (c < 2) ? gq0 : gq1;
                const bool valid = (key <= gq) && (key > gq - WIN);
                vmask[nt][c] = valid;
                const float s = valid ? sacc[nt][c] : -1e30f;
                sacc[nt][c] = s;
                if (c < 2) tmax0 = fmaxf(tmax0, s);
                else       tmax1 = fmaxf(tmax1, s);
            }
        }
        #pragma unroll
        for (int o = 1; o <= 2; o <<= 1) {
            tmax0 = fmaxf(tmax0, __shfl_xor_sync(0xffffffffu, tmax0, o));
            tmax1 = fmaxf(tmax1, __shfl_xor_sync(0xffffffffu, tmax1, o));
        }
        const float mn0 = fmaxf(m0, tmax0);
        const float mn1 = fmaxf(m1, tmax1);
        const float alpha0 = fexp2(m0 - mn0);
        const float alpha1 = fexp2(m1 - mn1);
        m0 = mn0; m1 = mn1;

        float rs0 = 0.f, rs1 = 0.f;
        #pragma unroll
        for (int nt = 0; nt < 4; nt++) {
            #pragma unroll
            for (int c = 0; c < 4; c++) {
                const float mn = (c < 2) ? mn0 : mn1;
                const float pv = vmask[nt][c] ? fexp2(sacc[nt][c] - mn) : 0.f;
                p[nt][c] = pv;
                if (c < 2) rs0 += pv; else rs1 += pv;
            }
        }
        #pragma unroll
        for (int o = 1; o <= 2; o <<= 1) {
            rs0 += __shfl_xor_sync(0xffffffffu, rs0, o);
            rs1 += __shfl_xor_sync(0xffffffffu, rs1, o);
        }
        l0 = l0 * alpha0 + rs0;
        l1 = l1 * alpha1 + rs1;

        #pragma unroll
        for (int nt = 0; nt < 16; nt++) {
            oacc[nt][0] *= alpha0; oacc[nt][1] *= alpha0;
            oacc[nt][2] *= alpha1; oacc[nt][3] *= alpha1;
        }

        __syncthreads();

        #pragma unroll
        for (int nt = 0; nt < 4; nt++) {
            const int col = nt * 8 + 2 * tig;
            *(float2*)&Pw[(gid    ) * PSTR + col] = make_float2(f2tf32(p[nt][0]), f2tf32(p[nt][1]));
            *(float2*)&Pw[(gid + 8) * PSTR + col] = make_float2(f2tf32(p[nt][2]), f2tf32(p[nt][3]));
        }
        __syncwarp();

        #pragma unroll
        for (int kk = 0; kk < 4; kk++) {
            const int kb = kk * 8;
            unsigned int pa[4];
            pa[0] = __float_as_uint(Pw[(gid    ) * PSTR + kb + tig    ]);
            pa[1] = __float_as_uint(Pw[(gid + 8) * PSTR + kb + tig    ]);
            pa[2] = __float_as_uint(Pw[(gid    ) * PSTR + kb + tig + 4]);
            pa[3] = __float_as_uint(Pw[(gid + 8) * PSTR + kb + tig + 4]);
            #pragma unroll
            for (int nt = 0; nt < 16; nt++) {
                unsigned int vb[2];
                vb[0] = __float_as_uint(Vs[(kb + tig    ) * VSTR + nt * 8 + gid]);
                vb[1] = __float_as_uint(Vs[(kb + tig + 4) * VSTR + nt * 8 + gid]);
                MMA_TF32(oacc[nt], pa, vb);
            }
        }
    }

    const float il0 = 1.f / l0;
    const float il1 = 1.f / l1;
    #pragma unroll
    for (int nt = 0; nt < 16; nt++) {
        const int col = nt * 8 + 2 * tig;
        *(float2*)&y[(size_t)gq0 * C_EMB + h * HD + col] =
            make_float2(f2tf32(oacc[nt][0] * il0), f2tf32(oacc[nt][1] * il0));
        *(float2*)&y[(size_t)gq1 * C_EMB + h * HD + col] =
            make_float2(f2tf32(oacc[nt][2] * il1), f2tf32(oacc[nt][3] * il1));
    }
}

// ---------------------------------------------------------------------------
extern "C" void kernel_launch(void* const* d_in, const int* in_sizes, int n_in,
                              void* d_out, int out_size)
{
    const float* x    = (const float*)d_in[0];
    const float* ve   = (const float*)d_in[1];
    const float* cosb = (const float*)d_in[2];
    const float* sinb = (const float*)d_in[3];
    const float* wq   = (const float*)d_in[4];
    const float* wk   = (const float*)d_in[5];
    const float* wv   = (const float*)d_in[6];
    const float* wg   = (const float*)d_in[7];
    const float* wp   = (const float*)d_in[8];
    float* out = (float*)d_out;

    float *q, *k, *v, *y, *xr, *wr;
    cudaGetSymbolAddress((void**)&q,  g_q);
    cudaGetSymbolAddress((void**)&k,  g_k);
    cudaGetSymbolAddress((void**)&v,  g_v);
    cudaGetSymbolAddress((void**)&y,  g_y);
    cudaGetSymbolAddress((void**)&xr, g_xr);
    cudaGetSymbolAddress((void**)&wr, g_wr);

    // 0. pre-round x and all weights (one launch)
    dim3 ra_grid(1024, 8);
    round_all_kernel<<<ra_grid, 256>>>(x, wq, wk, wv, wp, xr, wr);

    // 1. fused QKV projections (+gate on V)
    dim3 qkv_grid(24, T_LEN / 128);
    qkv_gemm_kernel<<<qkv_grid, 128>>>(xr, wr, q, k, v, x, ve, wg);

    // 2. RoPE + RMSNorm on q and k
    dim3 rr_grid(T_LEN, 2);
    rope_rms2_kernel<<<rr_grid, 256>>>(q, k, cosb, sinb);

    // 3. tensor-core sliding-window attention
    dim3 attn_grid(T_LEN / AQT, NH);        // (32, 8)
    attn_mma_kernel<<<attn_grid, 256>>>(q, k, v, y);

    // 4. output projection (BM=128, grid (8,32))
    dim3 gemm_grid(C_EMB / 128, T_LEN / 128);
    tf32_gemm_kernel<<<gemm_grid, 128>>>(y, wr + (size_t)3 * C_EMB * C_EMB, out);
}